// round 13
// baseline (speedup 1.0000x reference)
#include <cuda_runtime.h>
#include <cuda_bf16.h>
#include <cstdint>

// Problem constants (fixed shapes)
#define BATCH 2
#define SEQ   2048
#define DMODEL 2048
#define NH    32
#define NKV   8
#define HD    64
#define NTOK  (BATCH*SEQ)          // 4096

__device__ __forceinline__ float ex2(float x) {
    float r;
    asm("ex2.approx.ftz.f32 %0, %1;" : "=f"(r) : "f"(x));
    return r;
}

// ---------------- mma.sync / ldmatrix / cp.async helpers ----------------
__device__ __forceinline__ void ldsm4(uint32_t &r0, uint32_t &r1, uint32_t &r2, uint32_t &r3, uint32_t addr) {
    asm volatile("ldmatrix.sync.aligned.m8n8.x4.shared.b16 {%0,%1,%2,%3}, [%4];"
                 : "=r"(r0), "=r"(r1), "=r"(r2), "=r"(r3) : "r"(addr));
}
__device__ __forceinline__ void ldsm4t(uint32_t &r0, uint32_t &r1, uint32_t &r2, uint32_t &r3, uint32_t addr) {
    asm volatile("ldmatrix.sync.aligned.m8n8.x4.trans.shared.b16 {%0,%1,%2,%3}, [%4];"
                 : "=r"(r0), "=r"(r1), "=r"(r2), "=r"(r3) : "r"(addr));
}
// bf16 HMMA: D(f32) = A(bf16,row) * B(bf16,col) + D
__device__ __forceinline__ void hmma16816(float* c, const uint32_t* a, const uint32_t* b) {
    asm volatile("mma.sync.aligned.m16n8k16.row.col.f32.bf16.bf16.f32 "
                 "{%0,%1,%2,%3}, {%4,%5,%6,%7}, {%8,%9}, {%0,%1,%2,%3};"
                 : "+f"(c[0]), "+f"(c[1]), "+f"(c[2]), "+f"(c[3])
                 : "r"(a[0]), "r"(a[1]), "r"(a[2]), "r"(a[3]), "r"(b[0]), "r"(b[1]));
}
__device__ __forceinline__ void cp16(uint32_t dst, const void* src) {
    asm volatile("cp.async.cg.shared.global [%0], [%1], 16;" :: "r"(dst), "l"(src) : "memory");
}
#define CP_COMMIT() asm volatile("cp.async.commit_group;" ::: "memory")
#define CP_WAIT1()  asm volatile("cp.async.wait_group 1;" ::: "memory")
#define CP_WAIT0()  asm volatile("cp.async.wait_group 0;" ::: "memory")

// pack two f32 -> bf16x2 (v0 in low half)
__device__ __forceinline__ uint32_t bf16x2(float lo, float hi) {
    uint32_t r;
    asm("cvt.rn.bf16x2.f32 %0, %1, %2;" : "=r"(r) : "f"(hi), "f"(lo));
    return r;
}
// split two f32 into (hi bf16x2, residual-lo bf16x2): exact to ~2^-17
__device__ __forceinline__ void split_pair(float v0, float v1, uint32_t &h, uint32_t &l) {
    __nv_bfloat16 b0 = __float2bfloat16(v0);
    __nv_bfloat16 b1 = __float2bfloat16(v1);
    float r0 = v0 - __bfloat162float(b0);
    float r1 = v1 - __bfloat162float(b1);
    uint16_t u0 = *(uint16_t*)&b0, u1 = *(uint16_t*)&b1;
    h = (uint32_t)u0 | ((uint32_t)u1 << 16);
    l = bf16x2(r0, r1);
}

// ---------------- device scratch (static, allocation-free) ----------------
__device__ float g_partial[4*256];
__device__ float g_wscale[4];
__device__ __align__(16) __nv_bfloat16 g_wq[DMODEL*DMODEL];
__device__ __align__(16) __nv_bfloat16 g_wk[NKV*HD*DMODEL];
__device__ __align__(16) __nv_bfloat16 g_wv[NKV*HD*DMODEL];
__device__ __align__(16) __nv_bfloat16 g_wo[DMODEL*DMODEL];
__device__ __align__(16) __nv_bfloat16 g_xq0[NTOK*DMODEL];
__device__ __align__(16) __nv_bfloat16 g_xq1[NTOK*DMODEL];
__device__ __align__(16) __nv_bfloat16 g_xq2[NTOK*DMODEL];
__device__ __align__(16) __nv_bfloat16 g_xqo[NTOK*DMODEL];
__device__ float g_xs0[NTOK];
__device__ float g_xs1[NTOK];
__device__ float g_xs2[NTOK];
__device__ float g_xso[NTOK];
__device__ float g_projq[NTOK*DMODEL];     // [token, h*64+d]  (pre-rope)
__device__ float g_projk[NTOK*NKV*HD];     // [token, kv*64+d] (pre-rope)
__device__ float g_projv[NTOK*NKV*HD];
__device__ float g_attn[NTOK*DMODEL];      // [token, h*64+d]
// roped + split K/V in [b][kvh][t][64] bf16 layout (128B rows)
__device__ __align__(16) __nv_bfloat16 g_kh[BATCH*NKV*SEQ*HD];
__device__ __align__(16) __nv_bfloat16 g_kl[BATCH*NKV*SEQ*HD];
__device__ __align__(16) __nv_bfloat16 g_vh[BATCH*NKV*SEQ*HD];
__device__ __align__(16) __nv_bfloat16 g_vl[BATCH*NKV*SEQ*HD];

// ---------------- weight abs-mean: 4 matrices in one launch ----------------
__global__ void absum_all(const float* __restrict__ w0, const float* __restrict__ w1,
                          const float* __restrict__ w2, const float* __restrict__ w3) {
    __shared__ float red[256];
    const float* ws[4] = {w0, w1, w2, w3};
    const int    ns[4] = {DMODEL*DMODEL, NKV*HD*DMODEL, NKV*HD*DMODEL, DMODEL*DMODEL};
    int k = blockIdx.y;
    const float* w = ws[k];
    int n = ns[k];
    int tid = threadIdx.x;
    float s = 0.f;
    for (int i = blockIdx.x*256 + tid; i < n; i += 256*256) s += fabsf(w[i]);
    red[tid] = s; __syncthreads();
    for (int st = 128; st > 0; st >>= 1) { if (tid < st) red[tid] += red[tid+st]; __syncthreads(); }
    if (tid == 0) g_partial[k*256 + blockIdx.x] = red[0];
}

__global__ void finalize_wscale() {
    __shared__ float red[256];
    int tid = threadIdx.x;
    const float ninv[4] = {1.f/(2048.f*2048.f), 1.f/(512.f*2048.f),
                           1.f/(512.f*2048.f), 1.f/(2048.f*2048.f)};
    for (int k = 0; k < 4; k++) {
        red[tid] = g_partial[k*256 + tid]; __syncthreads();
        for (int st = 128; st > 0; st >>= 1) { if (tid < st) red[tid] += red[tid+st]; __syncthreads(); }
        if (tid == 0) g_wscale[k] = fmaxf(red[0]*ninv[k], 1e-5f);
        __syncthreads();
    }
}

// ---------------- ternary weight quant: 4 matrices in one launch (bf16 out, exact) ----------------
__global__ void quant_all(const float* __restrict__ w0, const float* __restrict__ w1,
                          const float* __restrict__ w2, const float* __restrict__ w3,
                          __nv_bfloat16* o0, __nv_bfloat16* o1, __nv_bfloat16* o2v, __nv_bfloat16* o3) {
    const float* ws[4] = {w0, w1, w2, w3};
    __nv_bfloat16* os[4] = {o0, o1, o2v, o3};
    const int    ns[4] = {DMODEL*DMODEL, NKV*HD*DMODEL, NKV*HD*DMODEL, DMODEL*DMODEL};
    int k = blockIdx.y;
    const float* w = ws[k];
    __nv_bfloat16* o = os[k];
    int n = ns[k];
    float inv = 1.f / g_wscale[k];
    for (int i = blockIdx.x*blockDim.x + threadIdx.x; i < n; i += gridDim.x*blockDim.x) {
        float q = rintf(w[i]*inv);
        q = fminf(fmaxf(q, -1.f), 1.f);
        o[i] = __float2bfloat16(q);   // {-1,0,1}: exact
    }
}

// ---------------- activation quant (rmsnorm + absmax int8-in-bf16), shuffle reductions ----------------
__global__ void act_quant(const float* __restrict__ x,
                          const float* g0, const float* g1, const float* g2,
                          __nv_bfloat16* xq0, __nv_bfloat16* xq1, __nv_bfloat16* xq2,
                          float* s0, float* s1, float* s2) {
    __shared__ float red8[9];
    int row = blockIdx.x, tid = threadIdx.x;
    const float4* xp = (const float4*)(x + (size_t)row*DMODEL);
    float4 xa = xp[tid*2], xb = xp[tid*2+1];
    float xv[8] = {xa.x, xa.y, xa.z, xa.w, xb.x, xb.y, xb.z, xb.w};
    float ss = 0.f;
    #pragma unroll
    for (int l = 0; l < 8; l++) ss += xv[l]*xv[l];
    #pragma unroll
    for (int m = 16; m; m >>= 1) ss += __shfl_xor_sync(0xffffffffu, ss, m);
    if ((tid & 31) == 0) red8[tid >> 5] = ss;
    __syncthreads();
    if (tid < 32) {
        float t = (tid < 8) ? red8[tid] : 0.f;
        #pragma unroll
        for (int m = 4; m; m >>= 1) t += __shfl_xor_sync(0xffffffffu, t, m);
        if (tid == 0) red8[8] = t;
    }
    __syncthreads();
    float rinv = rsqrtf(red8[8]*(1.f/(float)DMODEL) + 1e-6f);

    const float* gs[3] = {g0, g1, g2};
    __nv_bfloat16* xqs[3] = {xq0, xq1, xq2};
    float* scs[3] = {s0, s1, s2};
    for (int vI = 0; vI < 3; vI++) {
        const float* g = gs[vI];
        if (!g) continue;
        __syncthreads();
        const float4* gp = (const float4*)g;
        float4 ga = gp[tid*2], gb = gp[tid*2+1];
        float gv[8] = {ga.x, ga.y, ga.z, ga.w, gb.x, gb.y, gb.z, gb.w};
        float amax = 0.f, xn[8];
        #pragma unroll
        for (int l = 0; l < 8; l++) {
            float v = xv[l]*rinv*gv[l];
            xn[l] = v; amax = fmaxf(amax, fabsf(v));
        }
        #pragma unroll
        for (int m = 16; m; m >>= 1) amax = fmaxf(amax, __shfl_xor_sync(0xffffffffu, amax, m));
        if ((tid & 31) == 0) red8[tid >> 5] = amax;
        __syncthreads();
        if (tid < 32) {
            float t = (tid < 8) ? red8[tid] : 0.f;
            #pragma unroll
            for (int m = 4; m; m >>= 1) t = fmaxf(t, __shfl_xor_sync(0xffffffffu, t, m));
            if (tid == 0) red8[8] = t;
        }
        __syncthreads();
        float sc = fmaxf(red8[8], 1e-5f);
        float qf = 127.f/sc;
        float qv[8];
        #pragma unroll
        for (int l = 0; l < 8; l++) {
            int q = __float2int_rn(xn[l]*qf);
            qv[l] = (float)max(-128, min(127, q));   // small int, bf16-exact
        }
        uint4 pk;
        pk.x = bf16x2(qv[0], qv[1]);
        pk.y = bf16x2(qv[2], qv[3]);
        pk.z = bf16x2(qv[4], qv[5]);
        pk.w = bf16x2(qv[6], qv[7]);
        *(uint4*)(xqs[vI] + (size_t)row*DMODEL + tid*8) = pk;
        if (tid == 0) scs[vI][row] = sc;
    }
}

// ---------------- bf16 tensor-core GEMM (m16n8k16), 256x128 CTA tile, 512 threads ----------------
// smem (int4 units): A buf0 [0,2048), A buf1 [2048,4096), B buf0 [4096,5120), B buf1 [5120,6144) = 96KB
__device__ __forceinline__ void gemm_hmma_body(const __nv_bfloat16* A, const __nv_bfloat16* B,
                                               const float* xsc, int widx,
                                               float* C, int N, int m0, int n0) {
    extern __shared__ __align__(16) int4 gsm[];
    const int K = 2048;
    int tid = threadIdx.x;
    int lane = tid & 31, warp = tid >> 5;
    int warp_m = warp >> 2, warp_n = warp & 3;     // 4 x 4 warps, warp tile 64x32

    uint32_t sb = (uint32_t)__cvta_generic_to_shared(gsm);

    int g = lane >> 3, lr = lane & 7;
    int rowA_base = warp_m*64 + (g&1)*8 + lr;
    int rowB_base = warp_n*32 + (g>>1)*8 + lr;
    int acolg = g >> 1, bcolg = g & 1;
    int grow = tid >> 3, gcol = tid & 7;           // grow 0..63

    float c[4][4][4];
    #pragma unroll
    for (int mt = 0; mt < 4; mt++)
        #pragma unroll
        for (int nt = 0; nt < 4; nt++)
            #pragma unroll
            for (int i = 0; i < 4; i++) c[mt][nt][i] = 0.f;

    {
        #pragma unroll
        for (int l = 0; l < 4; l++) {
            int row = grow + l*64;
            uint32_t da = sb + (uint32_t)((row*8 + (gcol ^ (row & 7)))*16);
            cp16(da, A + (size_t)(m0 + row)*K + gcol*8);
        }
        #pragma unroll
        for (int l = 0; l < 2; l++) {
            int row = grow + l*64;
            uint32_t db = sb + (uint32_t)((4096 + row*8 + (gcol ^ (row & 7)))*16);
            cp16(db, B + (size_t)(n0 + row)*K + gcol*8);
        }
        CP_COMMIT();
    }

    for (int kb = 0; kb < 32; kb++) {
        int buf = kb & 1;
        if (kb < 31) {
            int nb = buf ^ 1;
            #pragma unroll
            for (int l = 0; l < 4; l++) {
                int row = grow + l*64;
                uint32_t da = sb + (uint32_t)((nb*2048 + row*8 + (gcol ^ (row & 7)))*16);
                cp16(da, A + (size_t)(m0 + row)*K + (kb+1)*64 + gcol*8);
            }
            #pragma unroll
            for (int l = 0; l < 2; l++) {
                int row = grow + l*64;
                uint32_t db = sb + (uint32_t)((4096 + nb*1024 + row*8 + (gcol ^ (row & 7)))*16);
                cp16(db, B + (size_t)(n0 + row)*K + (kb+1)*64 + gcol*8);
            }
            CP_COMMIT();
            CP_WAIT1();
        } else {
            CP_WAIT0();
        }
        __syncthreads();

        uint32_t asb = sb + (uint32_t)(buf*2048*16);
        uint32_t bsb = sb + (uint32_t)((4096 + buf*1024)*16);
        #pragma unroll
        for (int kk = 0; kk < 4; kk++) {
            uint32_t a[4][4];
            #pragma unroll
            for (int mt = 0; mt < 4; mt++) {
                int rowA = rowA_base + mt*16;
                uint32_t addr = asb + (uint32_t)(rowA*128 + (((kk*2 + acolg) ^ lr) << 4));
                ldsm4(a[mt][0], a[mt][1], a[mt][2], a[mt][3], addr);
            }
            uint32_t bfr[4][2];
            #pragma unroll
            for (int nt2 = 0; nt2 < 2; nt2++) {
                int rowB = rowB_base + nt2*16;
                uint32_t addr = bsb + (uint32_t)(rowB*128 + (((kk*2 + bcolg) ^ lr) << 4));
                uint32_t r0, r1, r2, r3;
                ldsm4(r0, r1, r2, r3, addr);
                bfr[nt2*2][0] = r0;   bfr[nt2*2][1] = r1;
                bfr[nt2*2+1][0] = r2; bfr[nt2*2+1][1] = r3;
            }
            #pragma unroll
            for (int mt = 0; mt < 4; mt++)
                #pragma unroll
                for (int nt = 0; nt < 4; nt++)
                    hmma16816(c[mt][nt], a[mt], bfr[nt]);
        }
        __syncthreads();
    }

    float wsc = g_wscale[widx] * (1.f/127.f);
    int lane4 = lane >> 2, lanec = (lane & 3)*2;
    #pragma unroll
    for (int mt = 0; mt < 4; mt++) {
        int r0 = m0 + warp_m*64 + mt*16 + lane4;
        float s0 = wsc * xsc[r0];
        float s1 = wsc * xsc[r0 + 8];
        #pragma unroll
        for (int nt = 0; nt < 4; nt++) {
            int col = n0 + warp_n*32 + nt*8 + lanec;
            float2 v0, v1;
            v0.x = c[mt][nt][0]*s0; v0.y = c[mt][nt][1]*s0;
            v1.x = c[mt][nt][2]*s1; v1.y = c[mt][nt][3]*s1;
            *(float2*)&C[(size_t)r0*N + col] = v0;
            *(float2*)&C[(size_t)(r0+8)*N + col] = v1;
        }
    }
}

// fused Q/K/V projection GEMM: grid.x = 16(q) + 4(k) + 4(v) = 24; grid.y = NTOK/256
__global__ __launch_bounds__(512, 1)
void gemm_qkv(const __nv_bfloat16* __restrict__ A0, const __nv_bfloat16* __restrict__ A1,
              const __nv_bfloat16* __restrict__ A2,
              const __nv_bfloat16* __restrict__ B0, const __nv_bfloat16* __restrict__ B1,
              const __nv_bfloat16* __restrict__ B2,
              const float* __restrict__ xs0, const float* __restrict__ xs1,
              const float* __restrict__ xs2,
              float* __restrict__ C0, float* __restrict__ C1, float* __restrict__ C2) {
    int bx = blockIdx.x;
    int m0 = blockIdx.y*256;
    if (bx < 16) {
        gemm_hmma_body(A0, B0, xs0, 0, C0, DMODEL, m0, bx*128);
    } else if (bx < 20) {
        gemm_hmma_body(A1, B1, xs1, 1, C1, NKV*HD, m0, (bx-16)*128);
    } else {
        gemm_hmma_body(A2, B2, xs2, 2, C2, NKV*HD, m0, (bx-20)*128);
    }
}

// single GEMM (output projection)
__global__ __launch_bounds__(512, 1)
void gemm_hmma(const __nv_bfloat16* __restrict__ A, const __nv_bfloat16* __restrict__ B,
               const float* __restrict__ xsc, int widx,
               float* __restrict__ C, int N) {
    gemm_hmma_body(A, B, xsc, widx, C, N, blockIdx.y*256, blockIdx.x*128);
}

// ---------------- prep K/V: rope + split into [b][kvh][t][64] bf16 buffers ----------------
__global__ void prep_kv(const float* __restrict__ projk, const float* __restrict__ projv,
                        const float* __restrict__ cs, const float* __restrict__ sn,
                        __nv_bfloat16* __restrict__ kh, __nv_bfloat16* __restrict__ kl,
                        __nv_bfloat16* __restrict__ vh, __nv_bfloat16* __restrict__ vl) {
    int idx = blockIdx.x*blockDim.x + threadIdx.x;   // NTOK*NKV*16
    int c4 = idx & 15;
    int row = idx >> 4;                 // token*8 + kvh
    int kvh = row & 7;
    int token = row >> 3;
    int t = token & (SEQ - 1);
    int b = token >> 11;

    const float* kp = projk + (size_t)token*(NKV*HD) + kvh*HD;
    float4 a = *(const float4*)&kp[c4*4];
    float4 p = *(const float4*)&kp[(c4^8)*4];
    float4 c = *(const float4*)&cs[t*HD + c4*4];
    float4 s = *(const float4*)&sn[t*HD + c4*4];
    float sgn = (c4 < 8) ? -1.f : 1.f;
    float v0 = a.x*c.x + sgn*p.x*s.x;
    float v1 = a.y*c.y + sgn*p.y*s.y;
    float v2 = a.z*c.z + sgn*p.z*s.z;
    float v3 = a.w*c.w + sgn*p.w*s.w;
    uint32_t h01, l01, h23, l23;
    split_pair(v0, v1, h01, l01);
    split_pair(v2, v3, h23, l23);
    size_t dst = ((size_t)(b*NKV + kvh)*SEQ + t)*HD + c4*4;
    uint2 ph; ph.x = h01; ph.y = h23;
    uint2 pl; pl.x = l01; pl.y = l23;
    *(uint2*)&kh[dst] = ph;
    *(uint2*)&kl[dst] = pl;

    const float* vp = projv + (size_t)token*(NKV*HD) + kvh*HD;
    float4 vv = *(const float4*)&vp[c4*4];
    split_pair(vv.x, vv.y, h01, l01);
    split_pair(vv.z, vv.w, h23, l23);
    ph.x = h01; ph.y = h23;
    pl.x = l01; pl.y = l23;
    *(uint2*)&vh[dst] = ph;
    *(uint2*)&vl[dst] = pl;
}

// ---------------- tensor-core causal flash attention, split-bf16, cp.async KV pipeline ----------------
// 8 warps x 16 q-rows = 128-row q tile; kv tile 64. RoPE+scale fused into Q fill only.
// smem: Qh[0,16K) Ql[16K,32K); KV buf0 @32K: Kh,Kl,Vh,Vl (8K each); KV buf1 @64K. Total 96K.
#define SQH 0
#define SQL 16384
#define SKV0 32768
#define KOFF_L 8192
#define VOFF_H 16384
#define VOFF_L 24576
#define ATT_SMEM 98304
#define QSC (0.125f * 1.4426950408889634f)

__global__ __launch_bounds__(256, 2)
void attn_mma(const float* __restrict__ Q,
              const __nv_bfloat16* __restrict__ KH, const __nv_bfloat16* __restrict__ KL,
              const __nv_bfloat16* __restrict__ VH, const __nv_bfloat16* __restrict__ VL,
              float* __restrict__ O,
              const float* __restrict__ cs, const float* __restrict__ sn) {
    extern __shared__ char smem[];
    uint32_t sb = (uint32_t)__cvta_generic_to_shared(smem);
    int tid = threadIdx.x;
    int lane = tid & 31, wid = tid >> 5;
    int qt = (gridDim.x - 1) - blockIdx.x;   // LPT
    int h = blockIdx.y, b = blockIdx.z;
    int q0 = qt*128, kvh = h >> 2;
    const float* Qb = Q + (size_t)(b*SEQ + q0)*DMODEL + h*HD;
    size_t kvbase = (size_t)(b*NKV + kvh)*SEQ*HD;
    const __nv_bfloat16* Khb = KH + kvbase;
    const __nv_bfloat16* Klb = KL + kvbase;
    const __nv_bfloat16* Vhb = VH + kvbase;
    const __nv_bfloat16* Vlb = VL + kvbase;

    // ---- fill Q tile: rope + scale + split, swizzled bf16 ----
    #pragma unroll
    for (int l = 0; l < 8; l++) {
        int idx = tid + l*256;            // 2048 = 128 rows x 16 col-groups(4)
        int r = idx >> 4, c4 = idx & 15;
        int t = q0 + r;
        float4 a = *(const float4*)&Qb[(size_t)r*DMODEL + c4*4];
        float4 p = *(const float4*)&Qb[(size_t)r*DMODEL + (c4^8)*4];
        float4 c = *(const float4*)&cs[t*HD + c4*4];
        float4 s = *(const float4*)&sn[t*HD + c4*4];
        float sgn = (c4 < 8) ? -1.f : 1.f;
        float v0 = (a.x*c.x + sgn*p.x*s.x)*QSC;
        float v1 = (a.y*c.y + sgn*p.y*s.y)*QSC;
        float v2 = (a.z*c.z + sgn*p.z*s.z)*QSC;
        float v3 = (a.w*c.w + sgn*p.w*s.w)*QSC;
        uint32_t h01, l01, h23, l23;
        split_pair(v0, v1, h01, l01);
        split_pair(v2, v3, h23, l23);
        int off = r*128 + (((c4>>1) ^ (r&7))<<4) + (c4&1)*8;
        *(uint32_t*)(smem + SQH + off)     = h01;
        *(uint32_t*)(smem + SQH + off + 4) = h23;
        *(uint32_t*)(smem + SQL + off)     = l01;
        *(uint32_t*)(smem + SQL + off + 4) = l23;
    }

    float o[8][4];
    #pragma unroll
    for (int t = 0; t < 8; t++)
        #pragma unroll
        for (int e = 0; e < 4; e++) o[t][e] = 0.f;
    float m0r = -1e30f, m1r = -1e30f, l0r = 0.f, l1r = 0.f;

    int ktmax = 2*qt + 1;
    int ktmax_w = 2*qt + ((wid >= 4) ? 1 : 0);

    // per-thread cp.async mapping for KV tiles: 2 x (row, group)
    int fr0 = tid >> 3,          fg0 = tid & 7;
    int fr1 = (tid + 256) >> 3,  fg1 = tid & 7;
    uint32_t fo0 = (uint32_t)(fr0*128 + ((fg0 ^ (fr0&7))<<4));
    uint32_t fo1 = (uint32_t)(fr1*128 + ((fg1 ^ (fr1&7))<<4));

    // prefetch kt=0 into buf 0
    {
        uint32_t base = sb + SKV0;
        cp16(base + fo0,          Khb + (size_t)fr0*HD + fg0*8);
        cp16(base + fo1,          Khb + (size_t)fr1*HD + fg1*8);
        cp16(base + KOFF_L + fo0, Klb + (size_t)fr0*HD + fg0*8);
        cp16(base + KOFF_L + fo1, Klb + (size_t)fr1*HD + fg1*8);
        cp16(base + VOFF_H + fo0, Vhb + (size_t)fr0*HD + fg0*8);
        cp16(base + VOFF_H + fo1, Vhb + (size_t)fr1*HD + fg1*8);
        cp16(base + VOFF_L + fo0, Vlb + (size_t)fr0*HD + fg0*8);
        cp16(base + VOFF_L + fo1, Vlb + (size_t)fr1*HD + fg1*8);
        CP_COMMIT();
    }

    for (int kt = 0; kt <= ktmax; kt++) {
        int buf = kt & 1;
        __syncthreads();   // all warps done reading buf^1 from iteration kt-1
        if (kt < ktmax) {
            int j1 = (kt+1)*64;
            uint32_t base = sb + SKV0 + (buf^1)*32768;
            cp16(base + fo0,          Khb + (size_t)(j1+fr0)*HD + fg0*8);
            cp16(base + fo1,          Khb + (size_t)(j1+fr1)*HD + fg1*8);
            cp16(base + KOFF_L + fo0, Klb + (size_t)(j1+fr0)*HD + fg0*8);
            cp16(base + KOFF_L + fo1, Klb + (size_t)(j1+fr1)*HD + fg1*8);
            cp16(base + VOFF_H + fo0, Vhb + (size_t)(j1+fr0)*HD + fg0*8);
            cp16(base + VOFF_H + fo1, Vhb + (size_t)(j1+fr1)*HD + fg1*8);
            cp16(base + VOFF_L + fo0, Vlb + (size_t)(j1+fr0)*HD + fg0*8);
            cp16(base + VOFF_L + fo1, Vlb + (size_t)(j1+fr1)*HD + fg1*8);
            CP_COMMIT();
            CP_WAIT1();
        } else {
            CP_WAIT0();
        }
        __syncthreads();   // buf data visible to all
        if (kt > ktmax_w) continue;

        int j0 = kt*64;
        uint32_t kvb = sb + SKV0 + buf*32768;

        // ---- S = QK^T via split-bf16 HMMA (QhKh + QhKl + QlKh) ----
        float sv[8][4];
        #pragma unroll
        for (int t = 0; t < 8; t++)
            #pragma unroll
            for (int e = 0; e < 4; e++) sv[t][e] = 0.f;

        int rowA = wid*16 + ((lane>>3)&1)*8 + (lane&7);
        int rowBb = ((lane>>4)&1)*8 + (lane&7);
        #pragma unroll
        for (int ks = 0; ks < 4; ks++) {
            int grpA = ks*2 + (lane>>4);
            uint32_t offA = (uint32_t)(rowA*128 + ((grpA ^ (rowA&7))<<4));
            uint32_t qh[4], ql[4];
            ldsm4(qh[0], qh[1], qh[2], qh[3], sb + SQH + offA);
            ldsm4(ql[0], ql[1], ql[2], ql[3], sb + SQL + offA);
            int grpB = ks*2 + ((lane>>3)&1);
            #pragma unroll
            for (int jp = 0; jp < 4; jp++) {
                int rowB = jp*16 + rowBb;
                uint32_t offB = (uint32_t)(rowB*128 + ((grpB ^ (rowB&7))<<4));
                uint32_t kh[4], kl[4];
                ldsm4(kh[0], kh[1], kh[2], kh[3], kvb + offB);
                ldsm4(kl[0], kl[1], kl[2], kl[3], kvb + KOFF_L + offB);
                uint32_t bh0[2] = {kh[0], kh[1]}, bh1[2] = {kh[2], kh[3]};
                uint32_t bl0[2] = {kl[0], kl[1]}, bl1[2] = {kl[2], kl[3]};
                hmma16816(sv[2*jp],   qh, bh0);
                hmma16816(sv[2*jp],   qh, bl0);
                hmma16816(sv[2*jp],   ql, bh0);
                hmma16816(sv[2*jp+1], qh, bh1);
                hmma16816(sv[2*jp+1], qh, bl1);
                hmma16816(sv[2*jp+1], ql, bh1);
            }
        }

        // ---- online softmax on fragments (exp2 domain) ----
        int r0g = q0 + wid*16 + (lane>>2);
        int r1g = r0g + 8;
        bool needmask = (kt >= 2*qt);
        float tm0 = -1e30f, tm1 = -1e30f;
        #pragma unroll
        for (int t = 0; t < 8; t++) {
            if (needmask) {
                int colb = j0 + t*8 + ((lane&3)<<1);
                if (colb     > r0g) sv[t][0] = -1e30f;
                if (colb + 1 > r0g) sv[t][1] = -1e30f;
                if (colb     > r1g) sv[t][2] = -1e30f;
                if (colb + 1 > r1g) sv[t][3] = -1e30f;
            }
            tm0 = fmaxf(tm0, fmaxf(sv[t][0], sv[t][1]));
            tm1 = fmaxf(tm1, fmaxf(sv[t][2], sv[t][3]));
        }
        tm0 = fmaxf(tm0, __shfl_xor_sync(0xffffffffu, tm0, 1));
        tm0 = fmaxf(tm0, __shfl_xor_sync(0xffffffffu, tm0, 2));
        tm1 = fmaxf(tm1, __shfl_xor_sync(0xffffffffu, tm1, 1));
        tm1 = fmaxf(tm1, __shfl_xor_sync(0xffffffffu, tm1, 2));
        float nm0 = fmaxf(m0r, tm0), nm1 = fmaxf(m1r, tm1);
        float corr0 = ex2(m0r - nm0), corr1 = ex2(m1r - nm1);
        m0r = nm0; m1r = nm1;
        float ts0 = 0.f, ts1 = 0.f;
        #pragma unroll
        for (int t = 0; t < 8; t++) {
            sv[t][0] = ex2(sv[t][0] - nm0); ts0 += sv[t][0];
            sv[t][1] = ex2(sv[t][1] - nm0); ts0 += sv[t][1];
            sv[t][2] = ex2(sv[t][2] - nm1); ts1 += sv[t][2];
            sv[t][3] = ex2(sv[t][3] - nm1); ts1 += sv[t][3];
        }
        ts0 += __shfl_xor_sync(0xffffffffu, ts0, 1);
        ts0 += __shfl_xor_sync(0xffffffffu, ts0, 2);
        ts1 += __shfl_xor_sync(0xffffffffu, ts1, 1);
        ts1 += __shfl_xor_sync(0xffffffffu, ts1, 2);
        l0r = l0r*corr0 + ts0;
        l1r = l1r*corr1 + ts1;
        #pragma unroll
        for (int t = 0; t < 8; t++) {
            o[t][0] *= corr0; o[t][1] *= corr0;
            o[t][2] *= corr1; o[t][3] *= corr1;
        }

        // ---- O += P V via split-bf16 HMMA (PhVh + PlVh + PhVl) ----
        int rowVb = ((lane>>3)&1)*8 + (lane&7);
        #pragma unroll
        for (int js = 0; js < 4; js++) {
            uint32_t pah[4], pal[4];
            split_pair(sv[2*js][0],   sv[2*js][1],   pah[0], pal[0]);
            split_pair(sv[2*js][2],   sv[2*js][3],   pah[1], pal[1]);
            split_pair(sv[2*js+1][0], sv[2*js+1][1], pah[2], pal[2]);
            split_pair(sv[2*js+1][2], sv[2*js+1][3], pah[3], pal[3]);
            int rowV = js*16 + rowVb;
            #pragma unroll
            for (int dp = 0; dp < 4; dp++) {
                int grpV = dp*2 + (lane>>4);
                uint32_t offV = (uint32_t)(rowV*128 + ((grpV ^ (rowV&7))<<4));
                uint32_t vh[4], vl[4];
                ldsm4t(vh[0], vh[1], vh[2], vh[3], kvb + VOFF_H + offV);
                ldsm4t(vl[0], vl[1], vl[2], vl[3], kvb + VOFF_L + offV);
                uint32_t bh0[2] = {vh[0], vh[1]}, bh1[2] = {vh[2], vh[3]};
                uint32_t bl0[2] = {vl[0], vl[1]}, bl1[2] = {vl[2], vl[3]};
                hmma16816(o[2*dp],   pah, bh0);
                hmma16816(o[2*dp],   pal, bh0);
                hmma16816(o[2*dp],   pah, bl0);
                hmma16816(o[2*dp+1], pah, bh1);
                hmma16816(o[2*dp+1], pal, bh1);
                hmma16816(o[2*dp+1], pah, bl1);
            }
        }
    }

    // ---- epilogue ----
    float inv0 = 1.f / l0r, inv1 = 1.f / l1r;
    int r0l = wid*16 + (lane>>2);
    float* Ob = O + (size_t)(b*SEQ + q0)*DMODEL + h*HD;
    #pragma unroll
    for (int t = 0; t < 8; t++) {
        int col = t*8 + ((lane&3)<<1);
        float2 v0, v1;
        v0.x = o[t][0]*inv0; v0.y = o[t][1]*inv0;
        v1.x = o[t][2]*inv1; v1.y = o[t][3]*inv1;
        *(float2*)&Ob[(size_t)r0l*DMODEL + col] = v0;
        *(float2*)&Ob[(size_t)(r0l+8)*DMODEL + col] = v1;
    }
}

// ---------------- launch ----------------
extern "C" void kernel_launch(void* const* d_in, const int* in_sizes, int n_in,
                              void* d_out, int out_size) {
    const float* x   = (const float*)d_in[0];
    const float* cs  = (const float*)d_in[1];
    const float* sn  = (const float*)d_in[2];
    const float* wq  = (const float*)d_in[3];
    const float* wk  = (const float*)d_in[4];
    const float* wv  = (const float*)d_in[5];
    const float* wo  = (const float*)d_in[6];
    const float* gq  = (const float*)d_in[7];
    const float* gk  = (const float*)d_in[8];
    const float* gv  = (const float*)d_in[9];
    const float* go  = (const float*)d_in[10];
    float* out = (float*)d_out;

    __nv_bfloat16 *wq_q, *wk_q, *wv_q, *wo_q, *xq0, *xq1, *xq2, *xqo;
    __nv_bfloat16 *kh, *kl, *vh, *vl;
    float *xs0, *xs1, *xs2, *xso, *projq, *projk, *projv, *attnb;
    cudaGetSymbolAddress((void**)&wq_q, g_wq);
    cudaGetSymbolAddress((void**)&wk_q, g_wk);
    cudaGetSymbolAddress((void**)&wv_q, g_wv);
    cudaGetSymbolAddress((void**)&wo_q, g_wo);
    cudaGetSymbolAddress((void**)&xq0, g_xq0);
    cudaGetSymbolAddress((void**)&xq1, g_xq1);
    cudaGetSymbolAddress((void**)&xq2, g_xq2);
    cudaGetSymbolAddress((void**)&xqo, g_xqo);
    cudaGetSymbolAddress((void**)&xs0, g_xs0);
    cudaGetSymbolAddress((void**)&xs1, g_xs1);
    cudaGetSymbolAddress((void**)&xs2, g_xs2);
    cudaGetSymbolAddress((void**)&xso, g_xso);
    cudaGetSymbolAddress((void**)&projq, g_projq);
    cudaGetSymbolAddress((void**)&projk, g_projk);
    cudaGetSymbolAddress((void**)&projv, g_projv);
    cudaGetSymbolAddress((void**)&attnb, g_attn);
    cudaGetSymbolAddress((void**)&kh, g_kh);
    cudaGetSymbolAddress((void**)&kl, g_kl);
    cudaGetSymbolAddress((void**)&vh, g_vh);
    cudaGetSymbolAddress((void**)&vl, g_vl);

    cudaFuncSetAttribute(attn_mma, cudaFuncAttributeMaxDynamicSharedMemorySize, ATT_SMEM);
    cudaFuncSetAttribute(gemm_qkv, cudaFuncAttributeMaxDynamicSharedMemorySize, 98304);
    cudaFuncSetAttribute(gemm_hmma, cudaFuncAttributeMaxDynamicSharedMemorySize, 98304);

    // weight scales + ternary quant (fused launches)
    absum_all<<<dim3(256, 4), 256>>>(wq, wk, wv, wo);
    finalize_wscale<<<1, 256>>>();
    quant_all<<<dim3(1024, 4), 256>>>(wq, wk, wv, wo, wq_q, wk_q, wv_q, wo_q);

    // activation quant (3 projections share x row + rmsnorm stat)
    act_quant<<<NTOK, 256>>>(x, gq, gk, gv, xq0, xq1, xq2, xs0, xs1, xs2);

    // projections: fused Q/K/V bf16 tensor GEMM, 256x128 tiles, 512 threads
    gemm_qkv<<<dim3(24, NTOK/256), 512, 98304>>>(xq0, xq1, xq2, wq_q, wk_q, wv_q,
                                                 xs0, xs1, xs2, projq, projk, projv);

    // K/V rope + split (once, shared by all heads/q-tiles)
    prep_kv<<<(NTOK*NKV*16)/256, 256>>>(projk, projv, cs, sn, kh, kl, vh, vl);

    // attention (tensor-core, split-bf16, cp.async KV pipeline)
    attn_mma<<<dim3(SEQ/128, NH, BATCH), 256, ATT_SMEM>>>(projq, kh, kl, vh, vl, attnb, cs, sn);

    // output bitlinear
    act_quant<<<NTOK, 256>>>(attnb, go, nullptr, nullptr, xqo, nullptr, nullptr, xso, nullptr, nullptr);
    gemm_hmma<<<dim3(DMODEL/128, NTOK/256), 512, 98304>>>(xqo, wo_q, xso, 3, out, DMODEL);
}

// round 14
// speedup vs baseline: 1.0388x; 1.0388x over previous
#include <cuda_runtime.h>
#include <cuda_bf16.h>
#include <cstdint>

// Problem constants (fixed shapes)
#define BATCH 2
#define SEQ   2048
#define DMODEL 2048
#define NH    32
#define NKV   8
#define HD    64
#define NTOK  (BATCH*SEQ)          // 4096

__device__ __forceinline__ float ex2(float x) {
    float r;
    asm("ex2.approx.ftz.f32 %0, %1;" : "=f"(r) : "f"(x));
    return r;
}

// ---------------- mma.sync / ldmatrix / cp.async helpers ----------------
__device__ __forceinline__ void ldsm4(uint32_t &r0, uint32_t &r1, uint32_t &r2, uint32_t &r3, uint32_t addr) {
    asm volatile("ldmatrix.sync.aligned.m8n8.x4.shared.b16 {%0,%1,%2,%3}, [%4];"
                 : "=r"(r0), "=r"(r1), "=r"(r2), "=r"(r3) : "r"(addr));
}
__device__ __forceinline__ void ldsm4t(uint32_t &r0, uint32_t &r1, uint32_t &r2, uint32_t &r3, uint32_t addr) {
    asm volatile("ldmatrix.sync.aligned.m8n8.x4.trans.shared.b16 {%0,%1,%2,%3}, [%4];"
                 : "=r"(r0), "=r"(r1), "=r"(r2), "=r"(r3) : "r"(addr));
}
// bf16 HMMA: D(f32) = A(bf16,row) * B(bf16,col) + D
__device__ __forceinline__ void hmma16816(float* c, const uint32_t* a, const uint32_t* b) {
    asm volatile("mma.sync.aligned.m16n8k16.row.col.f32.bf16.bf16.f32 "
                 "{%0,%1,%2,%3}, {%4,%5,%6,%7}, {%8,%9}, {%0,%1,%2,%3};"
                 : "+f"(c[0]), "+f"(c[1]), "+f"(c[2]), "+f"(c[3])
                 : "r"(a[0]), "r"(a[1]), "r"(a[2]), "r"(a[3]), "r"(b[0]), "r"(b[1]));
}
__device__ __forceinline__ void cp16(uint32_t dst, const void* src) {
    asm volatile("cp.async.cg.shared.global [%0], [%1], 16;" :: "r"(dst), "l"(src) : "memory");
}
#define CP_COMMIT() asm volatile("cp.async.commit_group;" ::: "memory")
#define CP_WAIT1()  asm volatile("cp.async.wait_group 1;" ::: "memory")
#define CP_WAIT0()  asm volatile("cp.async.wait_group 0;" ::: "memory")

// pack two f32 -> bf16x2 (v0 in low half)
__device__ __forceinline__ uint32_t bf16x2(float lo, float hi) {
    uint32_t r;
    asm("cvt.rn.bf16x2.f32 %0, %1, %2;" : "=r"(r) : "f"(hi), "f"(lo));
    return r;
}
// split two f32 into (hi bf16x2, residual-lo bf16x2): exact to ~2^-17
__device__ __forceinline__ void split_pair(float v0, float v1, uint32_t &h, uint32_t &l) {
    __nv_bfloat16 b0 = __float2bfloat16(v0);
    __nv_bfloat16 b1 = __float2bfloat16(v1);
    float r0 = v0 - __bfloat162float(b0);
    float r1 = v1 - __bfloat162float(b1);
    uint16_t u0 = *(uint16_t*)&b0, u1 = *(uint16_t*)&b1;
    h = (uint32_t)u0 | ((uint32_t)u1 << 16);
    l = bf16x2(r0, r1);
}

// ---------------- device scratch (static, allocation-free) ----------------
__device__ float g_partial[4*256];
__device__ float g_wscale[4];
__device__ __align__(16) __nv_bfloat16 g_wq[DMODEL*DMODEL];
__device__ __align__(16) __nv_bfloat16 g_wk[NKV*HD*DMODEL];
__device__ __align__(16) __nv_bfloat16 g_wv[NKV*HD*DMODEL];
__device__ __align__(16) __nv_bfloat16 g_wo[DMODEL*DMODEL];
__device__ __align__(16) __nv_bfloat16 g_xq0[NTOK*DMODEL];
__device__ __align__(16) __nv_bfloat16 g_xq1[NTOK*DMODEL];
__device__ __align__(16) __nv_bfloat16 g_xq2[NTOK*DMODEL];
__device__ __align__(16) __nv_bfloat16 g_xqo[NTOK*DMODEL];
__device__ float g_xs0[NTOK];
__device__ float g_xs1[NTOK];
__device__ float g_xs2[NTOK];
__device__ float g_xso[NTOK];
__device__ float g_projq[NTOK*DMODEL];     // [token, h*64+d]  (pre-rope)
__device__ float g_projk[NTOK*NKV*HD];     // [token, kv*64+d] (pre-rope)
__device__ float g_projv[NTOK*NKV*HD];
__device__ float g_attn[NTOK*DMODEL];      // [token, h*64+d]
// roped + split K/V in [b][kvh][t][64] bf16 layout (128B rows)
__device__ __align__(16) __nv_bfloat16 g_kh[BATCH*NKV*SEQ*HD];
__device__ __align__(16) __nv_bfloat16 g_kl[BATCH*NKV*SEQ*HD];
__device__ __align__(16) __nv_bfloat16 g_vh[BATCH*NKV*SEQ*HD];
__device__ __align__(16) __nv_bfloat16 g_vl[BATCH*NKV*SEQ*HD];

// ---------------- weight abs-mean: 4 matrices in one launch ----------------
__global__ void absum_all(const float* __restrict__ w0, const float* __restrict__ w1,
                          const float* __restrict__ w2, const float* __restrict__ w3) {
    __shared__ float red[256];
    const float* ws[4] = {w0, w1, w2, w3};
    const int    ns[4] = {DMODEL*DMODEL, NKV*HD*DMODEL, NKV*HD*DMODEL, DMODEL*DMODEL};
    int k = blockIdx.y;
    const float* w = ws[k];
    int n = ns[k];
    int tid = threadIdx.x;
    float s = 0.f;
    for (int i = blockIdx.x*256 + tid; i < n; i += 256*256) s += fabsf(w[i]);
    red[tid] = s; __syncthreads();
    for (int st = 128; st > 0; st >>= 1) { if (tid < st) red[tid] += red[tid+st]; __syncthreads(); }
    if (tid == 0) g_partial[k*256 + blockIdx.x] = red[0];
}

__global__ void finalize_wscale() {
    __shared__ float red[256];
    int tid = threadIdx.x;
    const float ninv[4] = {1.f/(2048.f*2048.f), 1.f/(512.f*2048.f),
                           1.f/(512.f*2048.f), 1.f/(2048.f*2048.f)};
    for (int k = 0; k < 4; k++) {
        red[tid] = g_partial[k*256 + tid]; __syncthreads();
        for (int st = 128; st > 0; st >>= 1) { if (tid < st) red[tid] += red[tid+st]; __syncthreads(); }
        if (tid == 0) g_wscale[k] = fmaxf(red[0]*ninv[k], 1e-5f);
        __syncthreads();
    }
}

// ---------------- ternary weight quant: 4 matrices in one launch (bf16 out, exact) ----------------
__global__ void quant_all(const float* __restrict__ w0, const float* __restrict__ w1,
                          const float* __restrict__ w2, const float* __restrict__ w3,
                          __nv_bfloat16* o0, __nv_bfloat16* o1, __nv_bfloat16* o2v, __nv_bfloat16* o3) {
    const float* ws[4] = {w0, w1, w2, w3};
    __nv_bfloat16* os[4] = {o0, o1, o2v, o3};
    const int    ns[4] = {DMODEL*DMODEL, NKV*HD*DMODEL, NKV*HD*DMODEL, DMODEL*DMODEL};
    int k = blockIdx.y;
    const float* w = ws[k];
    __nv_bfloat16* o = os[k];
    int n = ns[k];
    float inv = 1.f / g_wscale[k];
    for (int i = blockIdx.x*blockDim.x + threadIdx.x; i < n; i += gridDim.x*blockDim.x) {
        float q = rintf(w[i]*inv);
        q = fminf(fmaxf(q, -1.f), 1.f);
        o[i] = __float2bfloat16(q);   // {-1,0,1}: exact
    }
}

// ---------------- activation quant (rmsnorm + absmax int8-in-bf16), shuffle reductions ----------------
__global__ void act_quant(const float* __restrict__ x,
                          const float* g0, const float* g1, const float* g2,
                          __nv_bfloat16* xq0, __nv_bfloat16* xq1, __nv_bfloat16* xq2,
                          float* s0, float* s1, float* s2) {
    __shared__ float red8[9];
    int row = blockIdx.x, tid = threadIdx.x;
    const float4* xp = (const float4*)(x + (size_t)row*DMODEL);
    float4 xa = xp[tid*2], xb = xp[tid*2+1];
    float xv[8] = {xa.x, xa.y, xa.z, xa.w, xb.x, xb.y, xb.z, xb.w};
    float ss = 0.f;
    #pragma unroll
    for (int l = 0; l < 8; l++) ss += xv[l]*xv[l];
    #pragma unroll
    for (int m = 16; m; m >>= 1) ss += __shfl_xor_sync(0xffffffffu, ss, m);
    if ((tid & 31) == 0) red8[tid >> 5] = ss;
    __syncthreads();
    if (tid < 32) {
        float t = (tid < 8) ? red8[tid] : 0.f;
        #pragma unroll
        for (int m = 4; m; m >>= 1) t += __shfl_xor_sync(0xffffffffu, t, m);
        if (tid == 0) red8[8] = t;
    }
    __syncthreads();
    float rinv = rsqrtf(red8[8]*(1.f/(float)DMODEL) + 1e-6f);

    const float* gs[3] = {g0, g1, g2};
    __nv_bfloat16* xqs[3] = {xq0, xq1, xq2};
    float* scs[3] = {s0, s1, s2};
    for (int vI = 0; vI < 3; vI++) {
        const float* g = gs[vI];
        if (!g) continue;
        __syncthreads();
        const float4* gp = (const float4*)g;
        float4 ga = gp[tid*2], gb = gp[tid*2+1];
        float gv[8] = {ga.x, ga.y, ga.z, ga.w, gb.x, gb.y, gb.z, gb.w};
        float amax = 0.f, xn[8];
        #pragma unroll
        for (int l = 0; l < 8; l++) {
            float v = xv[l]*rinv*gv[l];
            xn[l] = v; amax = fmaxf(amax, fabsf(v));
        }
        #pragma unroll
        for (int m = 16; m; m >>= 1) amax = fmaxf(amax, __shfl_xor_sync(0xffffffffu, amax, m));
        if ((tid & 31) == 0) red8[tid >> 5] = amax;
        __syncthreads();
        if (tid < 32) {
            float t = (tid < 8) ? red8[tid] : 0.f;
            #pragma unroll
            for (int m = 4; m; m >>= 1) t = fmaxf(t, __shfl_xor_sync(0xffffffffu, t, m));
            if (tid == 0) red8[8] = t;
        }
        __syncthreads();
        float sc = fmaxf(red8[8], 1e-5f);
        float qf = 127.f/sc;
        float qv[8];
        #pragma unroll
        for (int l = 0; l < 8; l++) {
            int q = __float2int_rn(xn[l]*qf);
            qv[l] = (float)max(-128, min(127, q));   // small int, bf16-exact
        }
        uint4 pk;
        pk.x = bf16x2(qv[0], qv[1]);
        pk.y = bf16x2(qv[2], qv[3]);
        pk.z = bf16x2(qv[4], qv[5]);
        pk.w = bf16x2(qv[6], qv[7]);
        *(uint4*)(xqs[vI] + (size_t)row*DMODEL + tid*8) = pk;
        if (tid == 0) scs[vI][row] = sc;
    }
}

// ---------------- bf16 tensor-core GEMM (m16n8k16), 128x128 CTA tile, 256 threads ----------------
// smem (int4 units): A buf0 [0,1024), A buf1 [1024,2048), B buf0 [2048,3072), B buf1 [3072,4096) = 64KB
__device__ __forceinline__ void gemm_hmma_body(const __nv_bfloat16* A, const __nv_bfloat16* B,
                                               const float* xsc, int widx,
                                               float* C, int N, int m0, int n0) {
    extern __shared__ __align__(16) int4 gsm[];
    const int K = 2048;
    int tid = threadIdx.x;
    int lane = tid & 31, warp = tid >> 5;
    int warp_m = warp >> 2, warp_n = warp & 3;     // 2 x 4

    uint32_t sb = (uint32_t)__cvta_generic_to_shared(gsm);

    int g = lane >> 3, lr = lane & 7;
    int rowA_base = warp_m*64 + (g&1)*8 + lr;
    int rowB_base = warp_n*32 + (g>>1)*8 + lr;
    int acolg = g >> 1, bcolg = g & 1;
    int grow = tid >> 3, gcol = tid & 7;

    float c[4][4][4];
    #pragma unroll
    for (int mt = 0; mt < 4; mt++)
        #pragma unroll
        for (int nt = 0; nt < 4; nt++)
            #pragma unroll
            for (int i = 0; i < 4; i++) c[mt][nt][i] = 0.f;

    {
        #pragma unroll
        for (int l = 0; l < 4; l++) {
            int row = grow + l*32;
            uint32_t da = sb + (uint32_t)((row*8 + (gcol ^ (row & 7)))*16);
            cp16(da, A + (size_t)(m0 + row)*K + gcol*8);
            uint32_t db = sb + (uint32_t)((2048 + row*8 + (gcol ^ (row & 7)))*16);
            cp16(db, B + (size_t)(n0 + row)*K + gcol*8);
        }
        CP_COMMIT();
    }

    for (int kb = 0; kb < 32; kb++) {
        int buf = kb & 1;
        if (kb < 31) {
            int nb = buf ^ 1;
            #pragma unroll
            for (int l = 0; l < 4; l++) {
                int row = grow + l*32;
                uint32_t da = sb + (uint32_t)((nb*1024 + row*8 + (gcol ^ (row & 7)))*16);
                cp16(da, A + (size_t)(m0 + row)*K + (kb+1)*64 + gcol*8);
                uint32_t db = sb + (uint32_t)((2048 + nb*1024 + row*8 + (gcol ^ (row & 7)))*16);
                cp16(db, B + (size_t)(n0 + row)*K + (kb+1)*64 + gcol*8);
            }
            CP_COMMIT();
            CP_WAIT1();
        } else {
            CP_WAIT0();
        }
        __syncthreads();

        uint32_t asb = sb + (uint32_t)(buf*1024*16);
        uint32_t bsb = sb + (uint32_t)((2048 + buf*1024)*16);
        #pragma unroll
        for (int kk = 0; kk < 4; kk++) {
            uint32_t a[4][4];
            #pragma unroll
            for (int mt = 0; mt < 4; mt++) {
                int rowA = rowA_base + mt*16;
                uint32_t addr = asb + (uint32_t)(rowA*128 + (((kk*2 + acolg) ^ lr) << 4));
                ldsm4(a[mt][0], a[mt][1], a[mt][2], a[mt][3], addr);
            }
            uint32_t bfr[4][2];
            #pragma unroll
            for (int nt2 = 0; nt2 < 2; nt2++) {
                int rowB = rowB_base + nt2*16;
                uint32_t addr = bsb + (uint32_t)(rowB*128 + (((kk*2 + bcolg) ^ lr) << 4));
                uint32_t r0, r1, r2, r3;
                ldsm4(r0, r1, r2, r3, addr);
                bfr[nt2*2][0] = r0;   bfr[nt2*2][1] = r1;
                bfr[nt2*2+1][0] = r2; bfr[nt2*2+1][1] = r3;
            }
            #pragma unroll
            for (int mt = 0; mt < 4; mt++)
                #pragma unroll
                for (int nt = 0; nt < 4; nt++)
                    hmma16816(c[mt][nt], a[mt], bfr[nt]);
        }
        __syncthreads();
    }

    float wsc = g_wscale[widx] * (1.f/127.f);
    int lane4 = lane >> 2, lanec = (lane & 3)*2;
    #pragma unroll
    for (int mt = 0; mt < 4; mt++) {
        int r0 = m0 + warp_m*64 + mt*16 + lane4;
        float s0 = wsc * xsc[r0];
        float s1 = wsc * xsc[r0 + 8];
        #pragma unroll
        for (int nt = 0; nt < 4; nt++) {
            int col = n0 + warp_n*32 + nt*8 + lanec;
            float2 v0, v1;
            v0.x = c[mt][nt][0]*s0; v0.y = c[mt][nt][1]*s0;
            v1.x = c[mt][nt][2]*s1; v1.y = c[mt][nt][3]*s1;
            *(float2*)&C[(size_t)r0*N + col] = v0;
            *(float2*)&C[(size_t)(r0+8)*N + col] = v1;
        }
    }
}

// fused Q/K/V projection GEMM: grid.x = 16(q) + 4(k) + 4(v) = 24
__global__ __launch_bounds__(256)
void gemm_qkv(const __nv_bfloat16* __restrict__ A0, const __nv_bfloat16* __restrict__ A1,
              const __nv_bfloat16* __restrict__ A2,
              const __nv_bfloat16* __restrict__ B0, const __nv_bfloat16* __restrict__ B1,
              const __nv_bfloat16* __restrict__ B2,
              const float* __restrict__ xs0, const float* __restrict__ xs1,
              const float* __restrict__ xs2,
              float* __restrict__ C0, float* __restrict__ C1, float* __restrict__ C2) {
    int bx = blockIdx.x;
    int m0 = blockIdx.y*128;
    if (bx < 16) {
        gemm_hmma_body(A0, B0, xs0, 0, C0, DMODEL, m0, bx*128);
    } else if (bx < 20) {
        gemm_hmma_body(A1, B1, xs1, 1, C1, NKV*HD, m0, (bx-16)*128);
    } else {
        gemm_hmma_body(A2, B2, xs2, 2, C2, NKV*HD, m0, (bx-20)*128);
    }
}

// single GEMM (output projection)
__global__ __launch_bounds__(256)
void gemm_hmma(const __nv_bfloat16* __restrict__ A, const __nv_bfloat16* __restrict__ B,
               const float* __restrict__ xsc, int widx,
               float* __restrict__ C, int N) {
    gemm_hmma_body(A, B, xsc, widx, C, N, blockIdx.y*128, blockIdx.x*128);
}

// ---------------- prep K/V: rope + split into [b][kvh][t][64] bf16 buffers ----------------
__global__ void prep_kv(const float* __restrict__ projk, const float* __restrict__ projv,
                        const float* __restrict__ cs, const float* __restrict__ sn,
                        __nv_bfloat16* __restrict__ kh, __nv_bfloat16* __restrict__ kl,
                        __nv_bfloat16* __restrict__ vh, __nv_bfloat16* __restrict__ vl) {
    int idx = blockIdx.x*blockDim.x + threadIdx.x;   // NTOK*NKV*16
    int c4 = idx & 15;
    int row = idx >> 4;                 // token*8 + kvh
    int kvh = row & 7;
    int token = row >> 3;
    int t = token & (SEQ - 1);
    int b = token >> 11;

    const float* kp = projk + (size_t)token*(NKV*HD) + kvh*HD;
    float4 a = *(const float4*)&kp[c4*4];
    float4 p = *(const float4*)&kp[(c4^8)*4];
    float4 c = *(const float4*)&cs[t*HD + c4*4];
    float4 s = *(const float4*)&sn[t*HD + c4*4];
    float sgn = (c4 < 8) ? -1.f : 1.f;
    float v0 = a.x*c.x + sgn*p.x*s.x;
    float v1 = a.y*c.y + sgn*p.y*s.y;
    float v2 = a.z*c.z + sgn*p.z*s.z;
    float v3 = a.w*c.w + sgn*p.w*s.w;
    uint32_t h01, l01, h23, l23;
    split_pair(v0, v1, h01, l01);
    split_pair(v2, v3, h23, l23);
    size_t dst = ((size_t)(b*NKV + kvh)*SEQ + t)*HD + c4*4;
    uint2 ph; ph.x = h01; ph.y = h23;
    uint2 pl; pl.x = l01; pl.y = l23;
    *(uint2*)&kh[dst] = ph;
    *(uint2*)&kl[dst] = pl;

    const float* vp = projv + (size_t)token*(NKV*HD) + kvh*HD;
    float4 vv = *(const float4*)&vp[c4*4];
    split_pair(vv.x, vv.y, h01, l01);
    split_pair(vv.z, vv.w, h23, l23);
    ph.x = h01; ph.y = h23;
    pl.x = l01; pl.y = l23;
    *(uint2*)&vh[dst] = ph;
    *(uint2*)&vl[dst] = pl;
}

// ---------------- tensor-core causal flash attention, split-bf16, cp.async KV pipeline ----------------
// 8 warps x 16 q-rows = 128-row q tile; kv tile 64. RoPE+scale fused into Q fill only.
// smem: Qh[0,16K) Ql[16K,32K); KV buf0 @32K: Kh,Kl,Vh,Vl (8K each); KV buf1 @64K. Total 96K.
#define SQH 0
#define SQL 16384
#define SKV0 32768
#define KOFF_L 8192
#define VOFF_H 16384
#define VOFF_L 24576
#define ATT_SMEM 98304
#define QSC (0.125f * 1.4426950408889634f)

__global__ __launch_bounds__(256, 2)
void attn_mma(const float* __restrict__ Q,
              const __nv_bfloat16* __restrict__ KH, const __nv_bfloat16* __restrict__ KL,
              const __nv_bfloat16* __restrict__ VH, const __nv_bfloat16* __restrict__ VL,
              float* __restrict__ O,
              const float* __restrict__ cs, const float* __restrict__ sn) {
    extern __shared__ char smem[];
    uint32_t sb = (uint32_t)__cvta_generic_to_shared(smem);
    int tid = threadIdx.x;
    int lane = tid & 31, wid = tid >> 5;
    int qt = (gridDim.x - 1) - blockIdx.x;   // LPT
    int h = blockIdx.y, b = blockIdx.z;
    int q0 = qt*128, kvh = h >> 2;
    const float* Qb = Q + (size_t)(b*SEQ + q0)*DMODEL + h*HD;
    size_t kvbase = (size_t)(b*NKV + kvh)*SEQ*HD;
    const __nv_bfloat16* Khb = KH + kvbase;
    const __nv_bfloat16* Klb = KL + kvbase;
    const __nv_bfloat16* Vhb = VH + kvbase;
    const __nv_bfloat16* Vlb = VL + kvbase;

    // ---- fill Q tile: rope + scale + split, swizzled bf16 ----
    #pragma unroll
    for (int l = 0; l < 8; l++) {
        int idx = tid + l*256;            // 2048 = 128 rows x 16 col-groups(4)
        int r = idx >> 4, c4 = idx & 15;
        int t = q0 + r;
        float4 a = *(const float4*)&Qb[(size_t)r*DMODEL + c4*4];
        float4 p = *(const float4*)&Qb[(size_t)r*DMODEL + (c4^8)*4];
        float4 c = *(const float4*)&cs[t*HD + c4*4];
        float4 s = *(const float4*)&sn[t*HD + c4*4];
        float sgn = (c4 < 8) ? -1.f : 1.f;
        float v0 = (a.x*c.x + sgn*p.x*s.x)*QSC;
        float v1 = (a.y*c.y + sgn*p.y*s.y)*QSC;
        float v2 = (a.z*c.z + sgn*p.z*s.z)*QSC;
        float v3 = (a.w*c.w + sgn*p.w*s.w)*QSC;
        uint32_t h01, l01, h23, l23;
        split_pair(v0, v1, h01, l01);
        split_pair(v2, v3, h23, l23);
        int off = r*128 + (((c4>>1) ^ (r&7))<<4) + (c4&1)*8;
        *(uint32_t*)(smem + SQH + off)     = h01;
        *(uint32_t*)(smem + SQH + off + 4) = h23;
        *(uint32_t*)(smem + SQL + off)     = l01;
        *(uint32_t*)(smem + SQL + off + 4) = l23;
    }

    float o[8][4];
    #pragma unroll
    for (int t = 0; t < 8; t++)
        #pragma unroll
        for (int e = 0; e < 4; e++) o[t][e] = 0.f;
    float m0r = -1e30f, m1r = -1e30f, l0r = 0.f, l1r = 0.f;

    int ktmax = 2*qt + 1;
    int ktmax_w = 2*qt + ((wid >= 4) ? 1 : 0);

    // per-thread cp.async mapping for KV tiles: 2 x (row, group)
    int fr0 = tid >> 3,          fg0 = tid & 7;
    int fr1 = (tid + 256) >> 3,  fg1 = tid & 7;
    uint32_t fo0 = (uint32_t)(fr0*128 + ((fg0 ^ (fr0&7))<<4));
    uint32_t fo1 = (uint32_t)(fr1*128 + ((fg1 ^ (fr1&7))<<4));

    // prefetch kt=0 into buf 0
    {
        uint32_t base = sb + SKV0;
        cp16(base + fo0,          Khb + (size_t)fr0*HD + fg0*8);
        cp16(base + fo1,          Khb + (size_t)fr1*HD + fg1*8);
        cp16(base + KOFF_L + fo0, Klb + (size_t)fr0*HD + fg0*8);
        cp16(base + KOFF_L + fo1, Klb + (size_t)fr1*HD + fg1*8);
        cp16(base + VOFF_H + fo0, Vhb + (size_t)fr0*HD + fg0*8);
        cp16(base + VOFF_H + fo1, Vhb + (size_t)fr1*HD + fg1*8);
        cp16(base + VOFF_L + fo0, Vlb + (size_t)fr0*HD + fg0*8);
        cp16(base + VOFF_L + fo1, Vlb + (size_t)fr1*HD + fg1*8);
        CP_COMMIT();
    }

    for (int kt = 0; kt <= ktmax; kt++) {
        int buf = kt & 1;
        __syncthreads();   // all warps done reading buf^1 from iteration kt-1
        if (kt < ktmax) {
            int j1 = (kt+1)*64;
            uint32_t base = sb + SKV0 + (buf^1)*32768;
            cp16(base + fo0,          Khb + (size_t)(j1+fr0)*HD + fg0*8);
            cp16(base + fo1,          Khb + (size_t)(j1+fr1)*HD + fg1*8);
            cp16(base + KOFF_L + fo0, Klb + (size_t)(j1+fr0)*HD + fg0*8);
            cp16(base + KOFF_L + fo1, Klb + (size_t)(j1+fr1)*HD + fg1*8);
            cp16(base + VOFF_H + fo0, Vhb + (size_t)(j1+fr0)*HD + fg0*8);
            cp16(base + VOFF_H + fo1, Vhb + (size_t)(j1+fr1)*HD + fg1*8);
            cp16(base + VOFF_L + fo0, Vlb + (size_t)(j1+fr0)*HD + fg0*8);
            cp16(base + VOFF_L + fo1, Vlb + (size_t)(j1+fr1)*HD + fg1*8);
            CP_COMMIT();
            CP_WAIT1();
        } else {
            CP_WAIT0();
        }
        __syncthreads();   // buf data visible to all
        if (kt > ktmax_w) continue;

        int j0 = kt*64;
        uint32_t kvb = sb + SKV0 + buf*32768;

        // ---- S = QK^T via split-bf16 HMMA (QhKh + QhKl + QlKh) ----
        float sv[8][4];
        #pragma unroll
        for (int t = 0; t < 8; t++)
            #pragma unroll
            for (int e = 0; e < 4; e++) sv[t][e] = 0.f;

        int rowA = wid*16 + ((lane>>3)&1)*8 + (lane&7);
        int rowBb = ((lane>>4)&1)*8 + (lane&7);
        #pragma unroll
        for (int ks = 0; ks < 4; ks++) {
            int grpA = ks*2 + (lane>>4);
            uint32_t offA = (uint32_t)(rowA*128 + ((grpA ^ (rowA&7))<<4));
            uint32_t qh[4], ql[4];
            ldsm4(qh[0], qh[1], qh[2], qh[3], sb + SQH + offA);
            ldsm4(ql[0], ql[1], ql[2], ql[3], sb + SQL + offA);
            int grpB = ks*2 + ((lane>>3)&1);
            #pragma unroll
            for (int jp = 0; jp < 4; jp++) {
                int rowB = jp*16 + rowBb;
                uint32_t offB = (uint32_t)(rowB*128 + ((grpB ^ (rowB&7))<<4));
                uint32_t kh[4], kl[4];
                ldsm4(kh[0], kh[1], kh[2], kh[3], kvb + offB);
                ldsm4(kl[0], kl[1], kl[2], kl[3], kvb + KOFF_L + offB);
                uint32_t bh0[2] = {kh[0], kh[1]}, bh1[2] = {kh[2], kh[3]};
                uint32_t bl0[2] = {kl[0], kl[1]}, bl1[2] = {kl[2], kl[3]};
                hmma16816(sv[2*jp],   qh, bh0);
                hmma16816(sv[2*jp],   qh, bl0);
                hmma16816(sv[2*jp],   ql, bh0);
                hmma16816(sv[2*jp+1], qh, bh1);
                hmma16816(sv[2*jp+1], qh, bl1);
                hmma16816(sv[2*jp+1], ql, bh1);
            }
        }

        // ---- online softmax on fragments (exp2 domain) ----
        int r0g = q0 + wid*16 + (lane>>2);
        int r1g = r0g + 8;
        bool needmask = (kt >= 2*qt);
        float tm0 = -1e30f, tm1 = -1e30f;
        #pragma unroll
        for (int t = 0; t < 8; t++) {
            if (needmask) {
                int colb = j0 + t*8 + ((lane&3)<<1);
                if (colb     > r0g) sv[t][0] = -1e30f;
                if (colb + 1 > r0g) sv[t][1] = -1e30f;
                if (colb     > r1g) sv[t][2] = -1e30f;
                if (colb + 1 > r1g) sv[t][3] = -1e30f;
            }
            tm0 = fmaxf(tm0, fmaxf(sv[t][0], sv[t][1]));
            tm1 = fmaxf(tm1, fmaxf(sv[t][2], sv[t][3]));
        }
        tm0 = fmaxf(tm0, __shfl_xor_sync(0xffffffffu, tm0, 1));
        tm0 = fmaxf(tm0, __shfl_xor_sync(0xffffffffu, tm0, 2));
        tm1 = fmaxf(tm1, __shfl_xor_sync(0xffffffffu, tm1, 1));
        tm1 = fmaxf(tm1, __shfl_xor_sync(0xffffffffu, tm1, 2));
        float nm0 = fmaxf(m0r, tm0), nm1 = fmaxf(m1r, tm1);
        float corr0 = ex2(m0r - nm0), corr1 = ex2(m1r - nm1);
        m0r = nm0; m1r = nm1;
        float ts0 = 0.f, ts1 = 0.f;
        #pragma unroll
        for (int t = 0; t < 8; t++) {
            sv[t][0] = ex2(sv[t][0] - nm0); ts0 += sv[t][0];
            sv[t][1] = ex2(sv[t][1] - nm0); ts0 += sv[t][1];
            sv[t][2] = ex2(sv[t][2] - nm1); ts1 += sv[t][2];
            sv[t][3] = ex2(sv[t][3] - nm1); ts1 += sv[t][3];
        }
        ts0 += __shfl_xor_sync(0xffffffffu, ts0, 1);
        ts0 += __shfl_xor_sync(0xffffffffu, ts0, 2);
        ts1 += __shfl_xor_sync(0xffffffffu, ts1, 1);
        ts1 += __shfl_xor_sync(0xffffffffu, ts1, 2);
        l0r = l0r*corr0 + ts0;
        l1r = l1r*corr1 + ts1;
        #pragma unroll
        for (int t = 0; t < 8; t++) {
            o[t][0] *= corr0; o[t][1] *= corr0;
            o[t][2] *= corr1; o[t][3] *= corr1;
        }

        // ---- O += P V via split-bf16 HMMA (PhVh + PlVh + PhVl) ----
        int rowVb = ((lane>>3)&1)*8 + (lane&7);
        #pragma unroll
        for (int js = 0; js < 4; js++) {
            uint32_t pah[4], pal[4];
            split_pair(sv[2*js][0],   sv[2*js][1],   pah[0], pal[0]);
            split_pair(sv[2*js][2],   sv[2*js][3],   pah[1], pal[1]);
            split_pair(sv[2*js+1][0], sv[2*js+1][1], pah[2], pal[2]);
            split_pair(sv[2*js+1][2], sv[2*js+1][3], pah[3], pal[3]);
            int rowV = js*16 + rowVb;
            #pragma unroll
            for (int dp = 0; dp < 4; dp++) {
                int grpV = dp*2 + (lane>>4);
                uint32_t offV = (uint32_t)(rowV*128 + ((grpV ^ (rowV&7))<<4));
                uint32_t vh[4], vl[4];
                ldsm4t(vh[0], vh[1], vh[2], vh[3], kvb + VOFF_H + offV);
                ldsm4t(vl[0], vl[1], vl[2], vl[3], kvb + VOFF_L + offV);
                uint32_t bh0[2] = {vh[0], vh[1]}, bh1[2] = {vh[2], vh[3]};
                uint32_t bl0[2] = {vl[0], vl[1]}, bl1[2] = {vl[2], vl[3]};
                hmma16816(o[2*dp],   pah, bh0);
                hmma16816(o[2*dp],   pal, bh0);
                hmma16816(o[2*dp],   pah, bl0);
                hmma16816(o[2*dp+1], pah, bh1);
                hmma16816(o[2*dp+1], pal, bh1);
                hmma16816(o[2*dp+1], pah, bl1);
            }
        }
    }

    // ---- epilogue ----
    float inv0 = 1.f / l0r, inv1 = 1.f / l1r;
    int r0l = wid*16 + (lane>>2);
    float* Ob = O + (size_t)(b*SEQ + q0)*DMODEL + h*HD;
    #pragma unroll
    for (int t = 0; t < 8; t++) {
        int col = t*8 + ((lane&3)<<1);
        float2 v0, v1;
        v0.x = o[t][0]*inv0; v0.y = o[t][1]*inv0;
        v1.x = o[t][2]*inv1; v1.y = o[t][3]*inv1;
        *(float2*)&Ob[(size_t)r0l*DMODEL + col] = v0;
        *(float2*)&Ob[(size_t)(r0l+8)*DMODEL + col] = v1;
    }
}

// ---------------- launch ----------------
extern "C" void kernel_launch(void* const* d_in, const int* in_sizes, int n_in,
                              void* d_out, int out_size) {
    const float* x   = (const float*)d_in[0];
    const float* cs  = (const float*)d_in[1];
    const float* sn  = (const float*)d_in[2];
    const float* wq  = (const float*)d_in[3];
    const float* wk  = (const float*)d_in[4];
    const float* wv  = (const float*)d_in[5];
    const float* wo  = (const float*)d_in[6];
    const float* gq  = (const float*)d_in[7];
    const float* gk  = (const float*)d_in[8];
    const float* gv  = (const float*)d_in[9];
    const float* go  = (const float*)d_in[10];
    float* out = (float*)d_out;

    __nv_bfloat16 *wq_q, *wk_q, *wv_q, *wo_q, *xq0, *xq1, *xq2, *xqo;
    __nv_bfloat16 *kh, *kl, *vh, *vl;
    float *xs0, *xs1, *xs2, *xso, *projq, *projk, *projv, *attnb;
    cudaGetSymbolAddress((void**)&wq_q, g_wq);
    cudaGetSymbolAddress((void**)&wk_q, g_wk);
    cudaGetSymbolAddress((void**)&wv_q, g_wv);
    cudaGetSymbolAddress((void**)&wo_q, g_wo);
    cudaGetSymbolAddress((void**)&xq0, g_xq0);
    cudaGetSymbolAddress((void**)&xq1, g_xq1);
    cudaGetSymbolAddress((void**)&xq2, g_xq2);
    cudaGetSymbolAddress((void**)&xqo, g_xqo);
    cudaGetSymbolAddress((void**)&xs0, g_xs0);
    cudaGetSymbolAddress((void**)&xs1, g_xs1);
    cudaGetSymbolAddress((void**)&xs2, g_xs2);
    cudaGetSymbolAddress((void**)&xso, g_xso);
    cudaGetSymbolAddress((void**)&projq, g_projq);
    cudaGetSymbolAddress((void**)&projk, g_projk);
    cudaGetSymbolAddress((void**)&projv, g_projv);
    cudaGetSymbolAddress((void**)&attnb, g_attn);
    cudaGetSymbolAddress((void**)&kh, g_kh);
    cudaGetSymbolAddress((void**)&kl, g_kl);
    cudaGetSymbolAddress((void**)&vh, g_vh);
    cudaGetSymbolAddress((void**)&vl, g_vl);

    cudaFuncSetAttribute(attn_mma, cudaFuncAttributeMaxDynamicSharedMemorySize, ATT_SMEM);
    cudaFuncSetAttribute(gemm_qkv, cudaFuncAttributeMaxDynamicSharedMemorySize, 65536);
    cudaFuncSetAttribute(gemm_hmma, cudaFuncAttributeMaxDynamicSharedMemorySize, 65536);

    // weight scales + ternary quant (fused launches)
    absum_all<<<dim3(256, 4), 256>>>(wq, wk, wv, wo);
    finalize_wscale<<<1, 256>>>();
    quant_all<<<dim3(1024, 4), 256>>>(wq, wk, wv, wo, wq_q, wk_q, wv_q, wo_q);

    // activation quant (3 projections share x row + rmsnorm stat)
    act_quant<<<NTOK, 256>>>(x, gq, gk, gv, xq0, xq1, xq2, xs0, xs1, xs2);

    // projections: fused Q/K/V bf16 tensor GEMM, 128x128 tiles, 256 threads (R12 config)
    gemm_qkv<<<dim3(24, NTOK/128), 256, 65536>>>(xq0, xq1, xq2, wq_q, wk_q, wv_q,
                                                 xs0, xs1, xs2, projq, projk, projv);

    // K/V rope + split (once, shared by all heads/q-tiles)
    prep_kv<<<(NTOK*NKV*16)/256, 256>>>(projk, projv, cs, sn, kh, kl, vh, vl);

    // attention (tensor-core, split-bf16, cp.async KV pipeline)
    attn_mma<<<dim3(SEQ/128, NH, BATCH), 256, ATT_SMEM>>>(projq, kh, kl, vh, vl, attnb, cs, sn);

    // output bitlinear
    act_quant<<<NTOK, 256>>>(attnb, go, nullptr, nullptr, xqo, nullptr, nullptr, xso, nullptr, nullptr);
    gemm_hmma<<<dim3(DMODEL/128, NTOK/128), 256, 65536>>>(xqo, wo_q, xso, 3, out, DMODEL);
}